// round 6
// baseline (speedup 1.0000x reference)
#include <cuda_runtime.h>
#include <cstdint>

// VectorQuant: N=8, S=2048, C=4, K=512, V=64
// Per CTA: tile of 128 rows (fixed c). S = x . e^T via tcgen05 kind::tf32,
// then exact-fp32 rescore of candidates within MARGIN of the approx min.
// Falls back to an exact SIMT scan when compiled without sm_103a features.
// d_out layout: [out0: 8*2048*4*64][out1: 8*2048*4][out2: 8*2048*4]

#if defined(__CUDA_ARCH__) && (defined(__CUDA_ARCH_FEAT_SM103_ALL) || \
    (defined(__CUDA_ARCH_SPECIFIC__) && __CUDA_ARCH_SPECIFIC__ == 1030))
#define VQ_TC 1
#else
#define VQ_TC 0
#endif

#define NS     16384
#define CC     4
#define KK     512
#define VV     64
#define TPB    512
#define MTILE  128
#define NHALF  256
#define MARGIN 1.0f

// smem layout (float indices)
#define SM_B     0        // 32768 floats: two halves of 256x64, atom-blocked SW128
#define SM_A     32768    // 8192 floats: 128x64, atom-blocked SW128
#define SM_E2    40960    // 512 floats: ||e_k||^2
#define SM_PMIN  41472    // 512 floats: per-(g,row) approx min
#define SM_BD    41984    // 512 floats: per-(g,row) best exact d
#define SM_BK    42496    // 512 ints : per-(g,row) best k
#define SM_TPTR  43008    // tmem base ptr
#define SM_MBAR  43010    // mbarrier (8B aligned: 43010*4=172040)
#define SM_FLOATS 43016

static constexpr uint32_t IDESC_TF32 =
    (1u << 4)              // dtype = F32
    | (2u << 7)            // atype = TF32
    | (2u << 10)           // btype = TF32
    | ((NHALF / 8) << 17)  // N = 256
    | ((MTILE / 16) << 24);// M = 128

static constexpr uint64_t DESC_BASE_SW128 =
    (uint64_t(2) << 61) | (uint64_t(1) << 46) | (uint64_t(64) << 32) | (uint64_t(1) << 16);

__device__ __forceinline__ uint32_t smem_u32(const void* p) {
    uint32_t a;
    asm("{ .reg .u64 t; cvta.to.shared.u64 t, %1; cvt.u32.u64 %0, t; }" : "=r"(a) : "l"(p));
    return a;
}

// Swizzled byte offset of element (row, vbyte) in an atom-blocked SW128 tile.
// atom = 8 rows x 128B; atoms stacked row-major first (atomrows of them), then col.
__device__ __forceinline__ uint32_t swz(int row, int vbyte, int atomrows) {
    uint32_t b = (uint32_t)(((row >> 3) + (vbyte >> 7) * atomrows) * 1024
                            + (row & 7) * 128 + (vbyte & 127));
    return b ^ ((b >> 3) & 0x70);
}

#if VQ_TC
__device__ __forceinline__ uint32_t elect_one() {
    uint32_t pred;
    asm volatile("{\n\t.reg .pred p;\n\telect.sync _|p, 0xFFFFFFFF;\n\t"
                 "selp.b32 %0, 1, 0, p;\n\t}" : "=r"(pred));
    return pred;
}

__device__ __forceinline__ void mma_tf32_ss(uint32_t d_tmem, uint64_t a_desc,
                                            uint64_t b_desc, uint32_t idesc, bool en) {
    uint32_t e = en ? 1u : 0u;
    uint32_t z = 0u;
    asm volatile(
        "{\n\t.reg .pred p;\n\t"
        "setp.ne.u32 p, %5, 0;\n\t"
        "tcgen05.mma.cta_group::1.kind::tf32 [%0], %1, %2, %3, {%4, %4, %4, %4}, p;\n\t}"
        :: "r"(d_tmem), "l"(a_desc), "l"(b_desc), "r"(idesc), "r"(z), "r"(e)
        : "memory");
}

#define LDTM_X32(r, addr)                                                     \
    asm volatile("tcgen05.ld.sync.aligned.32x32b.x32.b32 "                    \
        "{%0, %1, %2, %3, %4, %5, %6, %7, %8, %9, %10, %11, %12, %13, %14, %15, " \
        " %16, %17, %18, %19, %20, %21, %22, %23, %24, %25, %26, %27, %28, %29, %30, %31}, [%32];" \
        : "=r"((r)[0]), "=r"((r)[1]), "=r"((r)[2]), "=r"((r)[3]),             \
          "=r"((r)[4]), "=r"((r)[5]), "=r"((r)[6]), "=r"((r)[7]),             \
          "=r"((r)[8]), "=r"((r)[9]), "=r"((r)[10]), "=r"((r)[11]),           \
          "=r"((r)[12]), "=r"((r)[13]), "=r"((r)[14]), "=r"((r)[15]),         \
          "=r"((r)[16]), "=r"((r)[17]), "=r"((r)[18]), "=r"((r)[19]),         \
          "=r"((r)[20]), "=r"((r)[21]), "=r"((r)[22]), "=r"((r)[23]),         \
          "=r"((r)[24]), "=r"((r)[25]), "=r"((r)[26]), "=r"((r)[27]),         \
          "=r"((r)[28]), "=r"((r)[29]), "=r"((r)[30]), "=r"((r)[31])          \
        : "r"(addr))

__device__ __forceinline__ void mbar_wait_parity(uint32_t mbar, uint32_t parity) {
    uint32_t done;
    asm volatile(
        "{\n\t.reg .pred p;\n\t"
        "mbarrier.try_wait.parity.acquire.cta.shared::cta.b64 p, [%1], %2;\n\t"
        "selp.b32 %0, 1, 0, p;\n\t}"
        : "=r"(done) : "r"(mbar), "r"(parity) : "memory");
    if (!done) {
        asm volatile(
            "{\n\t.reg .pred P1;\n\t"
            "WAIT_LOOP_%=:\n\t"
            "mbarrier.try_wait.parity.acquire.cta.shared::cta.b64 P1, [%0], %1, 0x989680;\n\t"
            "@P1 bra.uni WAIT_DONE_%=;\n\t"
            "bra.uni WAIT_LOOP_%=;\n\t"
            "WAIT_DONE_%=:\n\t}"
            :: "r"(mbar), "r"(parity) : "memory");
    }
}
#endif  // VQ_TC

extern __shared__ __align__(1024) float smem_dyn[];

__global__ void __launch_bounds__(TPB, 1)
vq_tc_kernel(const float* __restrict__ x, const float* __restrict__ emb,
             float* __restrict__ out0, float* __restrict__ out1,
             float* __restrict__ out2)
{
    char* smem = (char*)smem_dyn;
    const uint32_t smem_base = smem_u32(smem);
    const int tid = threadIdx.x;
    const int wid = tid >> 5;
    const int lid = tid & 31;
    const int g   = wid >> 2;      // col-block / K-quarter
    const int w   = wid & 3;       // TMEM lane partition
    const int row = w * 32 + lid;  // row within tile owned by this thread

    const int c    = blockIdx.y;
    const int tile = blockIdx.x;
    const float* ec = emb + (size_t)c * KK * VV;

#if VQ_TC
    const uint32_t mbar = smem_base + SM_MBAR * 4;
    // TMEM alloc (warp 0) + mbarrier init
    if (wid == 0) {
        asm volatile("tcgen05.alloc.cta_group::1.sync.aligned.shared::cta.b32 [%0], %1;"
                     :: "r"(smem_base + SM_TPTR * 4), "r"(512u) : "memory");
        asm volatile("tcgen05.relinquish_alloc_permit.cta_group::1.sync.aligned;");
    }
    if (tid == 0) {
        asm volatile("mbarrier.init.shared.b64 [%0], %1;" :: "r"(mbar), "r"(1u) : "memory");
    }
#endif

    // ---- Load B = emb[c] (512x64 fp32) into two atom-blocked SW128 halves ----
    {
        const float4* ec4 = (const float4*)ec;
        #pragma unroll
        for (int it = 0; it < 16; it++) {
            int idx = it * TPB + tid;          // 0..8191 float4s
            int k = idx >> 4;
            int j = idx & 15;
            float4 v = ec4[idx];
            int half = k >> 8, brow = k & 255;
            uint32_t off = SM_B * 4 + half * 65536 + swz(brow, j * 16, 32);
            *(float4*)(smem + off) = v;
        }
    }
    // ---- Load A = x tile (128x64 fp32) ----
    {
        #pragma unroll
        for (int it = 0; it < 4; it++) {
            int idx = it * TPB + tid;          // 0..2047 float4s
            int r = idx >> 4;
            int j = idx & 15;
            const float4* gp = (const float4*)(x + ((size_t)(tile * MTILE + r) * CC + c) * VV) + j;
            float4 v = *gp;
            uint32_t off = SM_A * 4 + swz(r, j * 16, 16);
            *(float4*)(smem + off) = v;
        }
    }
    // ---- e2[k] (exact fp32) ----
    {
        int k = tid;  // TPB == KK
        const float4* rp = (const float4*)(ec + (size_t)k * VV);
        float s = 0.f;
        #pragma unroll
        for (int i = 0; i < VV / 4; i++) {
            float4 v = rp[i];
            s += v.x * v.x + v.y * v.y + v.z * v.z + v.w * v.w;
        }
        smem_dyn[SM_E2 + k] = s;
    }

#if VQ_TC
    asm volatile("fence.proxy.async.shared::cta;" ::: "memory");
#endif
    __syncthreads();

#if VQ_TC
    uint32_t tmem_base;
    asm volatile("ld.shared.b32 %0, [%1];" : "=r"(tmem_base) : "r"(smem_base + SM_TPTR * 4));

    // ---- MMA: D[128, 512] = A . B^T (tf32, fp32 accum), 2 N-halves x 8 K-steps ----
    if (wid == 0 && elect_one()) {
        const uint64_t a_base = DESC_BASE_SW128 | (((smem_base + SM_A * 4) >> 4) & 0x3FFF);
        const uint32_t offA[8] = {0, 2, 4, 6, 1024, 1026, 1028, 1030};
        const uint32_t offB[8] = {0, 2, 4, 6, 2048, 2050, 2052, 2054};
        #pragma unroll
        for (int h = 0; h < 2; h++) {
            const uint64_t b_base = DESC_BASE_SW128 |
                (((smem_base + SM_B * 4 + h * 65536) >> 4) & 0x3FFF);
            #pragma unroll
            for (int s = 0; s < 8; s++) {
                mma_tf32_ss(tmem_base + h * NHALF, a_base + offA[s], b_base + offB[s],
                            IDESC_TF32, s > 0);
            }
        }
        asm volatile(
            "tcgen05.commit.cta_group::1.mbarrier::arrive::one.shared::cluster.b64 [%0];"
            :: "r"(mbar) : "memory");
    }

    mbar_wait_parity(mbar, 0);
    asm volatile("tcgen05.fence::after_thread_sync;" ::: "memory");

    // ---- Pass 1: per-thread approx min over this group's 128 cols ----
    float minv = 3.4e38f;
    #pragma unroll
    for (int j = 0; j < 4; j++) {
        uint32_t r32[32];
        LDTM_X32(r32, tmem_base + g * 128 + j * 32);
        asm volatile("tcgen05.wait::ld.sync.aligned;" ::: "memory");
        #pragma unroll
        for (int i = 0; i < 32; i++) {
            int k = g * 128 + j * 32 + i;
            float s = fmaf(-2.0f, __uint_as_float(r32[i]), smem_dyn[SM_E2 + k]);
            minv = fminf(minv, s);
        }
    }
    smem_dyn[SM_PMIN + g * 128 + row] = minv;
    __syncthreads();

    float rowmin = fminf(fminf(smem_dyn[SM_PMIN + row],       smem_dyn[SM_PMIN + 128 + row]),
                         fminf(smem_dyn[SM_PMIN + 256 + row], smem_dyn[SM_PMIN + 384 + row]));
    const float thresh = rowmin + MARGIN;

    // ---- Pass 2: exact-fp32 rescore of candidates (ascending k => first-index ties) ----
    float bestd = 3.4e38f;
    int bestk = 1 << 30;
    #pragma unroll
    for (int j = 0; j < 4; j++) {
        uint32_t r32[32];
        LDTM_X32(r32, tmem_base + g * 128 + j * 32);
        asm volatile("tcgen05.wait::ld.sync.aligned;" ::: "memory");
        #pragma unroll
        for (int i = 0; i < 32; i++) {
            int k = g * 128 + j * 32 + i;
            float s = fmaf(-2.0f, __uint_as_float(r32[i]), smem_dyn[SM_E2 + k]);
            if (s < thresh) {
                int half = k >> 8, brow = k & 255;
                const char* bb = smem + SM_B * 4 + half * 65536;
                const char* aa = smem + SM_A * 4;
                float d0 = 0.f, d1 = 0.f, d2 = 0.f, d3 = 0.f;
                #pragma unroll
                for (int v4 = 0; v4 < 16; v4++) {
                    float4 xv = *(const float4*)(aa + swz(row, v4 * 16, 16));
                    float4 ev = *(const float4*)(bb + swz(brow, v4 * 16, 32));
                    d0 = fmaf(xv.x, ev.x, d0);
                    d1 = fmaf(xv.y, ev.y, d1);
                    d2 = fmaf(xv.z, ev.z, d2);
                    d3 = fmaf(xv.w, ev.w, d3);
                }
                float dot = (d0 + d1) + (d2 + d3);
                float d = smem_dyn[SM_E2 + k] - 2.0f * dot;
                if (d < bestd) { bestd = d; bestk = k; }
            }
        }
    }
#else
    // ---- SIMT fallback: exact scan. Thread (g,row) handles k in [g*128,(g+1)*128) ----
    const char* aa = smem + SM_A * 4;
    float4 xv[16];
    #pragma unroll
    for (int v4 = 0; v4 < 16; v4++)
        xv[v4] = *(const float4*)(aa + swz(row, v4 * 16, 16));

    float bestd = 3.4e38f;
    int bestk = 1 << 30;
    for (int kk = 0; kk < 128; kk++) {
        int k = g * 128 + kk;
        int half = k >> 8, brow = k & 255;
        const char* bb = smem + SM_B * 4 + half * 65536;
        float d0 = 0.f, d1 = 0.f, d2 = 0.f, d3 = 0.f;
        #pragma unroll
        for (int v4 = 0; v4 < 16; v4++) {
            float4 ev = *(const float4*)(bb + swz(brow, v4 * 16, 32));
            d0 = fmaf(xv[v4].x, ev.x, d0);
            d1 = fmaf(xv[v4].y, ev.y, d1);
            d2 = fmaf(xv[v4].z, ev.z, d2);
            d3 = fmaf(xv[v4].w, ev.w, d3);
        }
        float dot = (d0 + d1) + (d2 + d3);
        float d = smem_dyn[SM_E2 + k] - 2.0f * dot;
        if (d < bestd) { bestd = d; bestk = k; }
    }
#endif

    smem_dyn[SM_BD + g * 128 + row] = bestd;
    ((int*)smem_dyn)[SM_BK + g * 128 + row] = bestk;
    __syncthreads();

    // ---- Combine across groups (ascending g = ascending k) + write outputs ----
    if (wid < 4) {
        float bd = smem_dyn[SM_BD + row];
        int bk = ((int*)smem_dyn)[SM_BK + row];
        #pragma unroll
        for (int gg = 1; gg < 4; gg++) {
            float d = smem_dyn[SM_BD + gg * 128 + row];
            int kk = ((int*)smem_dyn)[SM_BK + gg * 128 + row];
            if (d < bd) { bd = d; bk = kk; }
        }

        const int rglob = tile * MTILE + row;
        int half = bk >> 8, brow = bk & 255;
        const char* bb = smem + SM_B * 4 + half * 65536;
        const char* aax = smem + SM_A * 4;
        float4* o0 = (float4*)(out0 + ((size_t)rglob * CC + c) * VV);
        float ss = 0.f;
        #pragma unroll
        for (int v4 = 0; v4 < 16; v4++) {
            float4 xq = *(const float4*)(aax + swz(row, v4 * 16, 16));
            float4 ev = *(const float4*)(bb + swz(brow, v4 * 16, 32));
            float e0 = xq.x - ev.x;
            float e1 = xq.y - ev.y;
            float e2 = xq.z - ev.z;
            float e3 = xq.w - ev.w;
            ss += e0 * e0 + e1 * e1 + e2 * e2 + e3 * e3;
            o0[v4] = ev;
        }
        out1[(size_t)rglob * CC + c] = ss;
        out2[(size_t)rglob * CC + c] = ss;
    }

#if VQ_TC
    __syncthreads();
    if (wid == 0) {
        asm volatile("tcgen05.dealloc.cta_group::1.sync.aligned.b32 %0, %1;"
                     :: "r"(tmem_base), "r"(512u));
    }
#endif
}

extern "C" void kernel_launch(void* const* d_in, const int* in_sizes, int n_in,
                              void* d_out, int out_size) {
    const float* x   = (const float*)d_in[0];
    const float* emb = (const float*)d_in[1];
    float* out  = (float*)d_out;
    float* out0 = out;
    float* out1 = out + (size_t)NS * CC * VV;
    float* out2 = out1 + (size_t)NS * CC;

    size_t smem = (size_t)SM_FLOATS * sizeof(float);
    cudaFuncSetAttribute(vq_tc_kernel, cudaFuncAttributeMaxDynamicSharedMemorySize,
                         (int)smem);
    dim3 grid(NS / MTILE, CC);
    vq_tc_kernel<<<grid, TPB, smem>>>(x, emb, out0, out1, out2);
}